// round 11
// baseline (speedup 1.0000x reference)
#include <cuda_runtime.h>
#include <cstdint>

#define KTOP 500
#define CAND_MAX 4096
#define NBIN 4096
#define NTASK 336
#define SCAN_BUF 2048
#define NTH 512

// ---------------- global scratch (static device allocations) ----------------
__device__ unsigned long long g_cand[NTASK][CAND_MAX];
__device__ int g_cnt[NTASK];   // zero-initialized at load; restored at end of k_mainpost

__device__ __forceinline__ unsigned int mapf(float v) {
    unsigned int u = __float_as_uint(v);
    return (u & 0x80000000u) ? ~u : (u | 0x80000000u);
}
__device__ __forceinline__ float unmapf(unsigned int u) {
    return __uint_as_float((u & 0x80000000u) ? (u ^ 0x80000000u) : ~u);
}

__device__ __forceinline__ void task_info(int task, int& lev, int& img, int& cls,
                                          int& H, int& HW) {
    lev = (task < 112) ? 0 : ((task < 224) ? 1 : 2);
    int tt = task - lev * 112;
    img = tt / 7;
    cls = tt % 7;
    H = 192 >> lev;
    HW = H * H;
}

// ---------------- kernel 1: streaming compaction, smem-buffered ----------------
__global__ __launch_bounds__(512) void k_scan(
    const float* __restrict__ cls3, const float* __restrict__ cls4,
    const float* __restrict__ cls5)
{
    __shared__ unsigned long long s_buf[SCAN_BUF];
    __shared__ int s_cnt, s_base;

    int b = blockIdx.x;
    int task, chunk, nchunk;
    if (b < 448)      { task = b >> 2;          chunk = b & 3; nchunk = 4; }
    else if (b < 560) { task = 112 + (b - 448); chunk = 0;     nchunk = 1; }
    else              { task = 224 + (b - 560); chunk = 0;     nchunk = 1; }

    int lev, img, cls, H, HW;
    task_info(task, lev, img, cls, H, HW);

    const float* clsP = (lev == 0) ? cls3 : ((lev == 1) ? cls4 : cls5);
    float thf = (lev == 0) ? -1.55f : ((lev == 1) ? -2.10f : -2.80f);

    if (threadIdx.x == 0) s_cnt = 0;
    __syncthreads();

    int nv4 = HW >> 2;
    int start = chunk * 512 + threadIdx.x;
    int stride = nchunk * 512;

    const float4* p0 = (const float4*)(clsP + (size_t)(img * 24 + 0 * 8 + cls + 1) * HW);
    const float4* p1 = (const float4*)(clsP + (size_t)(img * 24 + 1 * 8 + cls + 1) * HW);
    const float4* p2 = (const float4*)(clsP + (size_t)(img * 24 + 2 * 8 + cls + 1) * HW);

    for (int i4 = start; i4 < nv4; i4 += stride) {
        float4 v0 = p0[i4];
        float4 v1 = p1[i4];
        float4 v2 = p2[i4];
        #pragma unroll
        for (int a = 0; a < 3; a++) {
            float4 v = (a == 0) ? v0 : (a == 1) ? v1 : v2;
            #pragma unroll
            for (int e = 0; e < 4; e++) {
                float f = (e == 0) ? v.x : (e == 1) ? v.y : (e == 2) ? v.z : v.w;
                if (f > thf) {
                    int pos = atomicAdd(&s_cnt, 1);
                    if (pos < SCAN_BUF) {
                        unsigned n = (unsigned)((i4 * 4 + e) * 3 + a);
                        s_buf[pos] = ((unsigned long long)mapf(f) << 32)
                                   | (unsigned long long)(~n);
                    }
                }
            }
        }
    }
    __syncthreads();

    int scnt = s_cnt;
    if (threadIdx.x == 0) {
        // overflow poisons the total so k_mainpost takes the exact fallback
        int rep = (scnt > SCAN_BUF) ? scnt + 100000 : scnt;
        s_base = atomicAdd(&g_cnt[task], rep);
    }
    __syncthreads();
    int base = s_base;
    int nf = min(scnt, SCAN_BUF);
    for (int i = threadIdx.x; i < nf; i += 512) {
        int p = base + i;
        if (p < CAND_MAX) g_cand[task][p] = s_buf[i];
    }
}

// ---------------- kernel 2: fused select/sort/decode + spatial-hash NMS ----------------
struct Fused {
    union {
        unsigned long long cand[CAND_MAX];                          // 32768 B
        struct { unsigned int hist[NBIN]; unsigned int scan[NTH]; } h;  // 18432 B
        unsigned long long sup[KTOP][8];                            // 32000 B (after decode)
    } big;
    float bx1[512], by1[512], bx2[512], by2[512], ar[512];          // 10240 B
    int cellcnt[1024];
    int cellstart[1024];
    unsigned short order[512];
    unsigned short cellid[512];
    unsigned long long keepw[8];
    float warpred[16][5];
    float red[5];
    int wtot[16];
    int T, cntAbove, cnt_s;
};

__device__ void find_thr(Fused& S, int need, int tid, int& T_out, int& above_out) {
    int t8 = tid * 8;
    unsigned hh[8];
    unsigned sum = 0;
    #pragma unroll
    for (int e = 0; e < 8; e++) { hh[e] = S.big.h.hist[t8 + e]; sum += hh[e]; }
    S.big.h.scan[tid] = sum;
    __syncthreads();
    for (int off = 1; off < NTH; off <<= 1) {
        unsigned add = (tid + off < NTH) ? S.big.h.scan[tid + off] : 0u;
        __syncthreads();
        S.big.h.scan[tid] += add;
        __syncthreads();
    }
    unsigned sfx = S.big.h.scan[tid];
    unsigned nxt = (tid < NTH - 1) ? S.big.h.scan[tid + 1] : 0u;
    if (sfx >= (unsigned)need && nxt < (unsigned)need) {
        unsigned c = nxt;
        for (int b = 7; b >= 0; b--) {
            if (c + hh[b] >= (unsigned)need) { S.T = t8 + b; S.cntAbove = (int)c; break; }
            c += hh[b];
        }
    }
    __syncthreads();
    T_out = S.T;
    above_out = S.cntAbove;
}

__device__ __forceinline__ float wmaxf(float v) {
    #pragma unroll
    for (int o = 16; o; o >>= 1) v = fmaxf(v, __shfl_xor_sync(0xFFFFFFFFu, v, o));
    return v;
}
__device__ __forceinline__ float wminf(float v) {
    #pragma unroll
    for (int o = 16; o; o >>= 1) v = fminf(v, __shfl_xor_sync(0xFFFFFFFFu, v, o));
    return v;
}

__global__ __launch_bounds__(NTH, 2) void k_mainpost(
    const float* __restrict__ cls3, const float* __restrict__ cls4, const float* __restrict__ cls5,
    const float* __restrict__ reg3, const float* __restrict__ reg4, const float* __restrict__ reg5,
    float* __restrict__ out)
{
    extern __shared__ unsigned char sraw[];
    Fused& S = *reinterpret_cast<Fused*>(sraw);
    const int tid = threadIdx.x;
    const int lane = tid & 31;
    const int wid = tid >> 5;

    int task = blockIdx.x;
    int lev, img, cls, H, HW;
    task_info(task, lev, img, cls, H, HW);
    const int W = H;
    const float stride = (float)(8 << lev);
    const float asize  = (float)(16 << lev);

    const float* clsP = (lev == 0) ? cls3 : ((lev == 1) ? cls4 : cls5);
    const float* regP = (lev == 0) ? reg3 : ((lev == 1) ? reg4 : reg5);
    const float* plane0 = clsP + (size_t)(img * 24 + 0 * 8 + cls + 1) * HW;
    const float* plane1 = clsP + (size_t)(img * 24 + 1 * 8 + cls + 1) * HW;
    const float* plane2 = clsP + (size_t)(img * 24 + 2 * 8 + cls + 1) * HW;
    const float* planes[3] = { plane0, plane1, plane2 };

    if (tid < 8) S.keepw[tid] = 0ull;

    int cnt = g_cnt[task];

    if (cnt >= KTOP && cnt <= CAND_MAX) {
        for (int i = tid; i < cnt; i += NTH) S.big.cand[i] = g_cand[task][i];
        __syncthreads();
    } else {
        // exact fallback: 12-bit histogram select over raw planes
        for (int i = tid; i < NBIN; i += NTH) S.big.h.hist[i] = 0;
        __syncthreads();
        for (int a = 0; a < 3; a++) {
            const float* p = planes[a];
            for (int i = tid; i < HW; i += NTH) {
                unsigned u = mapf(p[i]);
                int bin = (int)(u >> 20);
                unsigned m = __match_any_sync(__activemask(), bin);
                int leader = __ffs(m) - 1;
                if (lane == leader) atomicAdd(&S.big.h.hist[bin], (unsigned)__popc(m));
            }
        }
        __syncthreads();
        int T, above;
        find_thr(S, KTOP, tid, T, above);
        if (tid == 0) S.cnt_s = 0;
        __syncthreads();
        for (int a = 0; a < 3; a++) {
            const float* p = planes[a];
            for (int i = tid; i < HW; i += NTH) {
                unsigned u = mapf(p[i]);
                if ((int)(u >> 20) >= T) {
                    int pos = atomicAdd(&S.cnt_s, 1);
                    if (pos < CAND_MAX) {
                        unsigned n = (unsigned)(i * 3 + a);
                        S.big.cand[pos] = ((unsigned long long)u << 32) | (unsigned long long)(~n);
                    }
                }
            }
        }
        __syncthreads();
        cnt = S.cnt_s;

        if (cnt > CAND_MAX) {
            // NOTE: hist aliases cand; recompute from planes, refine on bits [19:8]
            for (int i = tid; i < NBIN; i += NTH) S.big.h.hist[i] = 0;
            __syncthreads();
            for (int a = 0; a < 3; a++) {
                const float* p = planes[a];
                for (int i = tid; i < HW; i += NTH) {
                    unsigned u = mapf(p[i]);
                    if ((int)(u >> 20) == T)
                        atomicAdd(&S.big.h.hist[(u >> 8) & 0xFFFu], 1u);
                }
            }
            __syncthreads();
            int T2, ab2;
            find_thr(S, KTOP - above, tid, T2, ab2);
            if (tid == 0) S.cnt_s = 0;
            __syncthreads();
            for (int a = 0; a < 3; a++) {
                const float* p = planes[a];
                for (int i = tid; i < HW; i += NTH) {
                    unsigned u = mapf(p[i]);
                    int bin = (int)(u >> 20);
                    if (bin > T || (bin == T && (int)((u >> 8) & 0xFFFu) >= T2)) {
                        int pos = atomicAdd(&S.cnt_s, 1);
                        if (pos < CAND_MAX) {
                            unsigned n = (unsigned)(i * 3 + a);
                            S.big.cand[pos] = ((unsigned long long)u << 32) | (unsigned long long)(~n);
                        }
                    }
                }
            }
            __syncthreads();
            cnt = S.cnt_s;
        }
        if (cnt > CAND_MAX) cnt = CAND_MAX;
    }

    // ---------- smem bitonic sort (descending), pad to M ----------
    {
        int M = 512;
        while (M < cnt) M <<= 1;
        for (int i = cnt + tid; i < M; i += NTH) S.big.cand[i] = 0ull;
        __syncthreads();
        for (int k = 2; k <= M; k <<= 1) {
            for (int j = k >> 1; j > 0; j >>= 1) {
                for (int i = tid; i < M; i += NTH) {
                    int ixj = i ^ j;
                    if (ixj > i) {
                        unsigned long long a = S.big.cand[i], b = S.big.cand[ixj];
                        bool sw = ((i & k) == 0) ? (a < b) : (a > b);
                        if (sw) { S.big.cand[i] = b; S.big.cand[ixj] = a; }
                    }
                }
                __syncthreads();
            }
        }
    }

    // ---------- decode top-500, write boxes/scores/labels, stash boxes in smem ----------
    long long tbase = (long long)((lev * 16 + img) * 7 + cls) * KTOP;
    float4* obox4 = (float4*)(out + tbase * 4);
    float* osc   = out + 672000 + tbase;
    float* olab  = out + 1008000 + tbase;

    {
        int r = tid;
        bool valid_bit = false;
        float bx1v = 0.0f, by1v = 0.0f, bx2v = 0.0f, by2v = 0.0f;
        if (r < KTOP) {
            unsigned long long key = S.big.cand[r];
            unsigned u = (unsigned)(key >> 32);
            unsigned n = ~((unsigned)key);
            float logit = unmapf(u);
            float score = __fdividef(1.0f, 1.0f + __expf(-logit));

            int a = (int)(n % 3u);
            int p = (int)(n / 3u);
            int x = p % W;
            int y = p / W;
            float sqv = (a == 0) ? 0.70710678118654752f : ((a == 1) ? 1.0f : 1.41421356237309505f);
            float wa = asize * sqv;
            float ha = asize / sqv;
            float cxa = ((float)x + 0.5f) * stride;
            float cya = ((float)y + 0.5f) * stride;

            size_t rb = (size_t)(img * 12 + a * 4) * HW + (size_t)p;
            float dx = regP[rb];
            float dy = regP[rb + HW];
            float dw = regP[rb + 2 * (size_t)HW];
            float dh = regP[rb + 3 * (size_t)HW];

            float cx = dx * wa + cxa;
            float cy = dy * ha + cya;
            float bw = __expf(dw) * wa;
            float bh = __expf(dh) * ha;
            bx1v = cx - 0.5f * bw; by1v = cy - 0.5f * bh;
            bx2v = cx + 0.5f * bw; by2v = cy + 0.5f * bh;

            obox4[r] = make_float4(bx1v, by1v, bx2v, by2v);
            osc[r] = score;
            olab[r] = (float)cls;
            valid_bit = (score > 0.05f);
        }
        unsigned b = __ballot_sync(0xFFFFFFFFu, valid_bit);
        if (lane == 0 && b) atomicOr(&S.keepw[wid], (unsigned long long)b << ((wid & 1) ? 32 : 0));
        // ^ careful: keepw index = r>>6 = wid>>1; shift by (wid&1)*32
        __syncthreads();   // cand reads complete before bx arrays (non-aliased) written? bx arrays separate; but sup aliases cand later
        S.bx1[tid] = bx1v; S.by1[tid] = by1v; S.bx2[tid] = bx2v; S.by2[tid] = by2v;
        S.ar[tid]  = (bx2v - bx1v) * (by2v - by1v);
    }
    __syncthreads();

    // fix keepw indexing (the ballot above used wrong index); recompute cleanly
    if (tid < 8) S.keepw[tid] = 0ull;
    __syncthreads();
    {
        bool valid_bit = false;
        if (tid < KTOP) {
            // score > 0.05 <=> logit > logit0; recompute from output to avoid re-deriving
            valid_bit = (osc[tid] > 0.05f);
        }
        unsigned b = __ballot_sync(0xFFFFFFFFu, valid_bit);
        if (lane == 0 && b)
            atomicOr(&S.keepw[tid >> 6], (unsigned long long)b << ((tid >> 5 & 1) * 32));
    }

    // ---------- zero sup matrix (reuses cand region; cand is dead) ----------
    for (int i = tid; i < KTOP * 8; i += NTH)
        (&S.big.sup[0][0])[i] = 0ull;
    for (int i = tid; i < 1024; i += NTH) S.cellcnt[i] = 0;
    __syncthreads();

    // ---------- spatial hash build ----------
    bool real = (tid < KTOP);
    float cx = 0.5f * (S.bx1[tid] + S.bx2[tid]);
    float cy = 0.5f * (S.by1[tid] + S.by2[tid]);
    float ext = fmaxf(S.bx2[tid] - S.bx1[tid], S.by2[tid] - S.by1[tid]);
    float rminx = real ? cx : 1e30f, rmaxx = real ? cx : -1e30f;
    float rminy = real ? cy : 1e30f, rmaxy = real ? cy : -1e30f;
    float rext  = real ? ext : 0.0f;
    rminx = wminf(rminx); rmaxx = wmaxf(rmaxx);
    rminy = wminf(rminy); rmaxy = wmaxf(rmaxy);
    rext  = wmaxf(rext);
    if (lane == 0) {
        S.warpred[wid][0] = rminx; S.warpred[wid][1] = rmaxx;
        S.warpred[wid][2] = rminy; S.warpred[wid][3] = rmaxy;
        S.warpred[wid][4] = rext;
    }
    __syncthreads();
    if (wid == 0) {
        float a0 = (lane < 16) ? S.warpred[lane][0] : 1e30f;
        float a1 = (lane < 16) ? S.warpred[lane][1] : -1e30f;
        float a2 = (lane < 16) ? S.warpred[lane][2] : 1e30f;
        float a3 = (lane < 16) ? S.warpred[lane][3] : -1e30f;
        float a4 = (lane < 16) ? S.warpred[lane][4] : 0.0f;
        a0 = wminf(a0); a1 = wmaxf(a1); a2 = wminf(a2); a3 = wmaxf(a3); a4 = wmaxf(a4);
        if (lane == 0) {
            S.red[0] = a0; S.red[1] = a1; S.red[2] = a2; S.red[3] = a3; S.red[4] = a4;
        }
    }
    __syncthreads();

    float minx = S.red[0], miny = S.red[2];
    float rx = S.red[1] - minx, ry = S.red[3] - miny;
    float cs = fmaxf(fmaxf(S.red[4], fmaxf(rx, ry) * (1.0f / 31.0f)), 1.0f) * 1.0001f;
    float inv_cs = 1.0f / cs;
    int ncx = min(32, (int)(rx * inv_cs) + 1);
    int ncy = min(32, (int)(ry * inv_cs) + 1);

    int cix = 0, ciy = 0;
    if (real) {
        cix = min(ncx - 1, max(0, (int)((cx - minx) * inv_cs)));
        ciy = min(ncy - 1, max(0, (int)((cy - miny) * inv_cs)));
        int cid = ciy * 32 + cix;
        S.cellid[tid] = (unsigned short)cid;
        atomicAdd(&S.cellcnt[cid], 1);
    }
    __syncthreads();

    // exclusive scan of 1024 cell counts (512 threads x 2)
    {
        int c0 = S.cellcnt[2 * tid], c1 = S.cellcnt[2 * tid + 1];
        int s = c0 + c1;
        int incl = s;
        #pragma unroll
        for (int o = 1; o < 32; o <<= 1) {
            int n = __shfl_up_sync(0xFFFFFFFFu, incl, o);
            if (lane >= o) incl += n;
        }
        if (lane == 31) S.wtot[wid] = incl;
        __syncthreads();
        if (wid == 0) {
            int t = (lane < 16) ? S.wtot[lane] : 0;
            int ti = t;
            #pragma unroll
            for (int o = 1; o < 32; o <<= 1) {
                int n = __shfl_up_sync(0xFFFFFFFFu, ti, o);
                if (lane >= o) ti += n;
            }
            if (lane < 16) S.wtot[lane] = ti - t;
        }
        __syncthreads();
        int woff = S.wtot[wid];
        int excl = woff + incl - s;
        S.cellstart[2 * tid] = excl;
        S.cellstart[2 * tid + 1] = excl + c0;
    }
    __syncthreads();

    if (real) {
        int pos = atomicAdd(&S.cellstart[S.cellid[tid]], 1);
        S.order[pos] = (unsigned short)tid;
    }
    __syncthreads();

    // sparse pair search: 3x3 neighbor cells, only j > i, set bit on IoU > 0.5
    if (real) {
        int i = tid;
        float ix1 = S.bx1[i], iy1 = S.by1[i], ix2 = S.bx2[i], iy2 = S.by2[i];
        float ai = S.ar[i];
        for (int dy = -1; dy <= 1; dy++) {
            int yy = ciy + dy;
            if (yy < 0 || yy >= ncy) continue;
            for (int dxl = -1; dxl <= 1; dxl++) {
                int xx = cix + dxl;
                if (xx < 0 || xx >= ncx) continue;
                int c = yy * 32 + xx;
                int e = S.cellstart[c];
                int b = e - S.cellcnt[c];
                for (int k = b; k < e; k++) {
                    int j = S.order[k];
                    if (j <= i) continue;
                    float xx1 = fmaxf(ix1, S.bx1[j]);
                    float yy1 = fmaxf(iy1, S.by1[j]);
                    float xx2 = fminf(ix2, S.bx2[j]);
                    float yy2 = fminf(iy2, S.by2[j]);
                    float inter = fmaxf(xx2 - xx1, 0.0f) * fmaxf(yy2 - yy1, 0.0f);
                    if (3.0f * inter > ai + S.ar[j])
                        atomicOr(&S.big.sup[i][j >> 6], 1ull << (j & 63));
                }
            }
        }
    }
    __syncthreads();

    // greedy NMS (warp 0): ffs-skip serial within word + parallel cross-word
    if (tid < 32) {
        for (int w = 0; w < 8; w++) {
            if (lane == 0) {
                unsigned long long snap = S.keepw[w];
                unsigned long long supm = 0ull, kept = 0ull, rem = snap;
                int base = w << 6;
                while (rem) {
                    int b0, b1 = -1, b2 = -1, b3 = -1;
                    unsigned long long s0, s1 = 0, s2 = 0, s3 = 0;
                    b0 = __ffsll((long long)rem) - 1; rem &= rem - 1;
                    s0 = S.big.sup[base + b0][w];
                    if (rem) { b1 = __ffsll((long long)rem) - 1; rem &= rem - 1; s1 = S.big.sup[base + b1][w]; }
                    if (rem) { b2 = __ffsll((long long)rem) - 1; rem &= rem - 1; s2 = S.big.sup[base + b2][w]; }
                    if (rem) { b3 = __ffsll((long long)rem) - 1; rem &= rem - 1; s3 = S.big.sup[base + b3][w]; }
                    if (!((supm >> b0) & 1ull)) { kept |= 1ull << b0; supm |= s0; }
                    if (b1 >= 0 && !((supm >> b1) & 1ull)) { kept |= 1ull << b1; supm |= s1; }
                    if (b2 >= 0 && !((supm >> b2) & 1ull)) { kept |= 1ull << b2; supm |= s2; }
                    if (b3 >= 0 && !((supm >> b3) & 1ull)) { kept |= 1ull << b3; supm |= s3; }
                }
                S.keepw[w] = kept;
            }
            __syncwarp();
            int w2 = w + 1 + lane;
            if (lane < 7 && w2 < 8) {
                unsigned long long kept = S.keepw[w];
                unsigned long long acc = 0ull;
                int base = w << 6;
                while (kept) {
                    int b = __ffsll((long long)kept) - 1; kept &= kept - 1;
                    acc |= S.big.sup[base + b][w2];
                }
                S.keepw[w2] &= ~acc;
            }
            __syncwarp();
        }
    }
    __syncthreads();

    float* okeep = out + 840000 + tbase;
    for (int r = tid; r < KTOP; r += NTH)
        okeep[r] = ((S.keepw[r >> 6] >> (r & 63)) & 1ull) ? 1.0f : 0.0f;
    if (tid == 0) g_cnt[task] = 0;   // restore invariant for next graph replay
}

// ---------------- launcher ----------------
extern "C" void kernel_launch(void* const* d_in, const int* in_sizes, int n_in,
                              void* d_out, int out_size) {
    const float *cls3 = nullptr, *cls4 = nullptr, *cls5 = nullptr;
    const float *reg3 = nullptr, *reg4 = nullptr, *reg5 = nullptr;
    for (int i = 0; i < n_in; i++) {
        switch (in_sizes[i]) {
            case 14155776: cls3 = (const float*)d_in[i]; break;
            case 7077888:  reg3 = (const float*)d_in[i]; break;
            case 3538944:  cls4 = (const float*)d_in[i]; break;
            case 1769472:  reg4 = (const float*)d_in[i]; break;
            case 884736:   cls5 = (const float*)d_in[i]; break;
            case 442368:   reg5 = (const float*)d_in[i]; break;
        }
    }
    float* out = (float*)d_out;
    cudaFuncSetAttribute(k_mainpost, cudaFuncAttributeMaxDynamicSharedMemorySize,
                         (int)sizeof(Fused));
    k_scan<<<672, 512>>>(cls3, cls4, cls5);
    k_mainpost<<<NTASK, NTH, sizeof(Fused)>>>(cls3, cls4, cls5, reg3, reg4, reg5, out);
}

// round 12
// speedup vs baseline: 1.6357x; 1.6357x over previous
#include <cuda_runtime.h>
#include <cstdint>

#define KTOP 500
#define CAND_MAX 4096
#define NBIN 4096
#define NTASK 336
#define SCAN_BUF 2048

// ---------------- global scratch (static device allocations) ----------------
__device__ unsigned long long g_cand[NTASK][CAND_MAX];
__device__ int g_cnt[NTASK];                         // zero at load; restored by k_post
__device__ float4 g_boxes[NTASK][512];
__device__ unsigned long long g_keep[NTASK][8];

__device__ __forceinline__ unsigned int mapf(float v) {
    unsigned int u = __float_as_uint(v);
    return (u & 0x80000000u) ? ~u : (u | 0x80000000u);
}
__device__ __forceinline__ float unmapf(unsigned int u) {
    return __uint_as_float((u & 0x80000000u) ? (u ^ 0x80000000u) : ~u);
}

__device__ __forceinline__ void task_info(int task, int& lev, int& img, int& cls,
                                          int& H, int& HW) {
    lev = (task < 112) ? 0 : ((task < 224) ? 1 : 2);
    int tt = task - lev * 112;
    img = tt / 7;
    cls = tt % 7;
    H = 192 >> lev;
    HW = H * H;
}

// ---------------- kernel 1: streaming compaction, smem-buffered ----------------
__global__ __launch_bounds__(512, 4) void k_scan(
    const float* __restrict__ cls3, const float* __restrict__ cls4,
    const float* __restrict__ cls5)
{
    __shared__ unsigned long long s_buf[SCAN_BUF];
    __shared__ int s_cnt, s_base;

    int b = blockIdx.x;
    int task, chunk, nchunk;
    if (b < 448)      { task = b >> 2;          chunk = b & 3; nchunk = 4; }
    else if (b < 560) { task = 112 + (b - 448); chunk = 0;     nchunk = 1; }
    else              { task = 224 + (b - 560); chunk = 0;     nchunk = 1; }

    int lev, img, cls, H, HW;
    task_info(task, lev, img, cls, H, HW);

    const float* clsP = (lev == 0) ? cls3 : ((lev == 1) ? cls4 : cls5);
    float thf = (lev == 0) ? -1.55f : ((lev == 1) ? -2.10f : -2.80f);

    if (threadIdx.x == 0) s_cnt = 0;
    __syncthreads();

    int nv4 = HW >> 2;
    int start = chunk * 512 + threadIdx.x;
    int stride = nchunk * 512;

    const float4* p0 = (const float4*)(clsP + (size_t)(img * 24 + 0 * 8 + cls + 1) * HW);
    const float4* p1 = (const float4*)(clsP + (size_t)(img * 24 + 1 * 8 + cls + 1) * HW);
    const float4* p2 = (const float4*)(clsP + (size_t)(img * 24 + 2 * 8 + cls + 1) * HW);

    for (int i4 = start; i4 < nv4; i4 += stride) {
        float4 v0 = p0[i4];
        float4 v1 = p1[i4];
        float4 v2 = p2[i4];
        #pragma unroll
        for (int a = 0; a < 3; a++) {
            float4 v = (a == 0) ? v0 : (a == 1) ? v1 : v2;
            #pragma unroll
            for (int e = 0; e < 4; e++) {
                float f = (e == 0) ? v.x : (e == 1) ? v.y : (e == 2) ? v.z : v.w;
                if (f > thf) {
                    int pos = atomicAdd(&s_cnt, 1);
                    if (pos < SCAN_BUF) {
                        unsigned n = (unsigned)((i4 * 4 + e) * 3 + a);
                        s_buf[pos] = ((unsigned long long)mapf(f) << 32)
                                   | (unsigned long long)(~n);
                    }
                }
            }
        }
    }
    __syncthreads();

    int scnt = s_cnt;
    if (threadIdx.x == 0) {
        int rep = (scnt > SCAN_BUF) ? scnt + 100000 : scnt;  // poison -> exact fallback
        s_base = atomicAdd(&g_cnt[task], rep);
    }
    __syncthreads();
    int base = s_base;
    int nf = min(scnt, SCAN_BUF);
    for (int i = threadIdx.x; i < nf; i += 512) {
        int p = base + i;
        if (p < CAND_MAX) g_cand[task][p] = s_buf[i];
    }
}

// ---------------- kernel 2: sort + decode + outputs ----------------
struct SmemMain {
    union {
        struct { unsigned int hist[NBIN]; unsigned int scan[1024]; } h;
        unsigned long long cand[CAND_MAX];
    } u;
    unsigned long long keepw[8];
    int T, cntAbove, cnt;
};

__device__ void find_thr(SmemMain& S, int need, int tid, int& T_out, int& above_out) {
    int t4 = tid * 4;
    unsigned h0 = S.u.h.hist[t4], h1 = S.u.h.hist[t4 + 1];
    unsigned h2 = S.u.h.hist[t4 + 2], h3 = S.u.h.hist[t4 + 3];
    S.u.h.scan[tid] = h0 + h1 + h2 + h3;
    __syncthreads();
    for (int off = 1; off < 1024; off <<= 1) {
        unsigned add = (tid + off < 1024) ? S.u.h.scan[tid + off] : 0u;
        __syncthreads();
        S.u.h.scan[tid] += add;
        __syncthreads();
    }
    unsigned sfx = S.u.h.scan[tid];
    unsigned nxt = (tid < 1023) ? S.u.h.scan[tid + 1] : 0u;
    if (sfx >= (unsigned)need && nxt < (unsigned)need) {
        unsigned c = nxt;
        unsigned hh[4] = { h0, h1, h2, h3 };
        for (int b = 3; b >= 0; b--) {
            if (c + hh[b] >= (unsigned)need) { S.T = t4 + b; S.cntAbove = (int)c; break; }
            c += hh[b];
        }
    }
    __syncthreads();
    T_out = S.T;
    above_out = S.cntAbove;
}

__global__ __launch_bounds__(1024, 2) void k_main(
    const float* __restrict__ cls3, const float* __restrict__ cls4, const float* __restrict__ cls5,
    const float* __restrict__ reg3, const float* __restrict__ reg4, const float* __restrict__ reg5,
    float* __restrict__ out)
{
    __shared__ SmemMain S;
    const int tid = threadIdx.x;
    const int lane = tid & 31;

    int task = blockIdx.x;
    int lev, img, cls, H, HW;
    task_info(task, lev, img, cls, H, HW);
    const int W = H;
    const float stride = (float)(8 << lev);
    const float asize  = (float)(16 << lev);

    const float* clsP = (lev == 0) ? cls3 : ((lev == 1) ? cls4 : cls5);
    const float* regP = (lev == 0) ? reg3 : ((lev == 1) ? reg4 : reg5);
    const float* plane0 = clsP + (size_t)(img * 24 + 0 * 8 + cls + 1) * HW;
    const float* plane1 = clsP + (size_t)(img * 24 + 1 * 8 + cls + 1) * HW;
    const float* plane2 = clsP + (size_t)(img * 24 + 2 * 8 + cls + 1) * HW;
    const float* planes[3] = { plane0, plane1, plane2 };

    if (tid < 8) S.keepw[tid] = 0ull;
    __syncthreads();

    int cnt = g_cnt[task];

    if (cnt >= KTOP && cnt <= CAND_MAX) {
        for (int i = tid; i < cnt; i += 1024) S.u.cand[i] = g_cand[task][i];
        __syncthreads();
    } else {
        // exact fallback: 12-bit histogram select over raw planes
        for (int i = tid; i < NBIN; i += 1024) S.u.h.hist[i] = 0;
        __syncthreads();
        for (int a = 0; a < 3; a++) {
            const float* p = planes[a];
            for (int i = tid; i < HW; i += 1024) {
                unsigned u = mapf(p[i]);
                int bin = (int)(u >> 20);
                unsigned m = __match_any_sync(__activemask(), bin);
                int leader = __ffs(m) - 1;
                if (lane == leader) atomicAdd(&S.u.h.hist[bin], (unsigned)__popc(m));
            }
        }
        __syncthreads();
        int T, above;
        find_thr(S, KTOP, tid, T, above);
        if (tid == 0) S.cnt = 0;
        __syncthreads();
        for (int a = 0; a < 3; a++) {
            const float* p = planes[a];
            for (int i = tid; i < HW; i += 1024) {
                unsigned u = mapf(p[i]);
                if ((int)(u >> 20) >= T) {
                    int pos = atomicAdd(&S.cnt, 1);
                    if (pos < CAND_MAX) {
                        unsigned n = (unsigned)(i * 3 + a);
                        S.u.cand[pos] = ((unsigned long long)u << 32) | (unsigned long long)(~n);
                    }
                }
            }
        }
        __syncthreads();
        cnt = S.cnt;

        if (cnt > CAND_MAX) {
            for (int i = tid; i < NBIN; i += 1024) S.u.h.hist[i] = 0;
            __syncthreads();
            for (int a = 0; a < 3; a++) {
                const float* p = planes[a];
                for (int i = tid; i < HW; i += 1024) {
                    unsigned u = mapf(p[i]);
                    if ((int)(u >> 20) == T)
                        atomicAdd(&S.u.h.hist[(u >> 8) & 0xFFFu], 1u);
                }
            }
            __syncthreads();
            int T2, ab2;
            find_thr(S, KTOP - above, tid, T2, ab2);
            if (tid == 0) S.cnt = 0;
            __syncthreads();
            for (int a = 0; a < 3; a++) {
                const float* p = planes[a];
                for (int i = tid; i < HW; i += 1024) {
                    unsigned u = mapf(p[i]);
                    int bin = (int)(u >> 20);
                    if (bin > T || (bin == T && (int)((u >> 8) & 0xFFFu) >= T2)) {
                        int pos = atomicAdd(&S.cnt, 1);
                        if (pos < CAND_MAX) {
                            unsigned n = (unsigned)(i * 3 + a);
                            S.u.cand[pos] = ((unsigned long long)u << 32) | (unsigned long long)(~n);
                        }
                    }
                }
            }
            __syncthreads();
            cnt = S.cnt;
        }
        if (cnt > CAND_MAX) cnt = CAND_MAX;
    }

    // smem bitonic sort (descending), pad to M; j<16 steps are intra-warp
    {
        int M = 512;
        while (M < cnt) M <<= 1;
        for (int i = cnt + tid; i < M; i += 1024) S.u.cand[i] = 0ull;
        __syncthreads();
        for (int k = 2; k <= M; k <<= 1) {
            for (int j = k >> 1; j > 0; j >>= 1) {
                if (j >= 16) __syncthreads(); else __syncwarp();
                for (int i = tid; i < M; i += 1024) {
                    int ixj = i ^ j;
                    if (ixj > i) {
                        unsigned long long a = S.u.cand[i], b = S.u.cand[ixj];
                        bool sw = ((i & k) == 0) ? (a < b) : (a > b);
                        if (sw) { S.u.cand[i] = b; S.u.cand[ixj] = a; }
                    }
                }
            }
        }
        __syncthreads();
    }

    // decode top-500, write boxes/scores/labels + box scratch
    long long tbase = (long long)((lev * 16 + img) * 7 + cls) * KTOP;
    float4* obox4 = (float4*)(out + tbase * 4);
    float* osc   = out + 672000 + tbase;
    float* olab  = out + 1008000 + tbase;

    if (tid < 512) {
        int r = tid;
        bool valid_bit = false;
        if (r < KTOP) {
            unsigned long long key = S.u.cand[r];
            unsigned u = (unsigned)(key >> 32);
            unsigned n = ~((unsigned)key);
            float logit = unmapf(u);
            float score = __fdividef(1.0f, 1.0f + __expf(-logit));

            int a = (int)(n % 3u);
            int p = (int)(n / 3u);
            int x = p % W;
            int y = p / W;
            float sqv = (a == 0) ? 0.70710678118654752f : ((a == 1) ? 1.0f : 1.41421356237309505f);
            float wa = asize * sqv;
            float ha = asize / sqv;
            float cxa = ((float)x + 0.5f) * stride;
            float cya = ((float)y + 0.5f) * stride;

            size_t rb = (size_t)(img * 12 + a * 4) * HW + (size_t)p;
            float dx = regP[rb];
            float dy = regP[rb + HW];
            float dw = regP[rb + 2 * (size_t)HW];
            float dh = regP[rb + 3 * (size_t)HW];

            float cx = dx * wa + cxa;
            float cy = dy * ha + cya;
            float bw = __expf(dw) * wa;
            float bh = __expf(dh) * ha;
            float bx1 = cx - 0.5f * bw, by1 = cy - 0.5f * bh;
            float bx2 = cx + 0.5f * bw, by2 = cy + 0.5f * bh;

            float4 bxv = make_float4(bx1, by1, bx2, by2);
            g_boxes[task][r] = bxv;
            obox4[r] = bxv;
            osc[r] = score;
            olab[r] = (float)cls;
            valid_bit = (score > 0.05f);
        } else {
            g_boxes[task][r] = make_float4(0.0f, 0.0f, 0.0f, 0.0f);
        }
        unsigned b = __ballot_sync(0xFFFFFFFFu, valid_bit);
        if (lane == 0 && b)
            atomicOr(&S.keepw[r >> 6], (unsigned long long)b << ((r >> 5 & 1) * 32));
    }
    __syncthreads();
    if (tid < 8) g_keep[task][tid] = S.keepw[tid];
}

// ---------------- kernel 3: spatial-hash sparse IoU + sparse greedy NMS ----------------
struct PostSmem {
    unsigned long long sup[KTOP][8];
    float bx1[512], by1[512], bx2[512], by2[512], ar[512];
    int cnt[1024];
    int start[1024];
    unsigned short order[512];
    unsigned short cellid[512];
    unsigned long long keepw[8];
    unsigned long long supmark[8];     // rows with any outgoing suppression bits
    float warpred[16][5];
    float red[5];
    int wtot[16];
};

__device__ __forceinline__ float wmaxf(float v) {
    #pragma unroll
    for (int o = 16; o; o >>= 1) v = fmaxf(v, __shfl_xor_sync(0xFFFFFFFFu, v, o));
    return v;
}
__device__ __forceinline__ float wminf(float v) {
    #pragma unroll
    for (int o = 16; o; o >>= 1) v = fminf(v, __shfl_xor_sync(0xFFFFFFFFu, v, o));
    return v;
}

__global__ __launch_bounds__(512) void k_post(float* __restrict__ out) {
    extern __shared__ unsigned char sraw[];
    PostSmem& S = *reinterpret_cast<PostSmem*>(sraw);
    int task = blockIdx.x;
    int tid = threadIdx.x;
    int lane = tid & 31;
    int wid = tid >> 5;

    {
        float4 b = g_boxes[task][tid];
        S.bx1[tid] = b.x; S.by1[tid] = b.y; S.bx2[tid] = b.z; S.by2[tid] = b.w;
        S.ar[tid] = (b.z - b.x) * (b.w - b.y);
    }
    for (int i = tid; i < KTOP * 8; i += 512)
        (&S.sup[0][0])[i] = 0ull;
    for (int i = tid; i < 1024; i += 512) S.cnt[i] = 0;
    if (tid < 8) { S.keepw[tid] = g_keep[task][tid]; S.supmark[tid] = 0ull; }
    __syncthreads();

    bool real = (tid < KTOP);
    float cx = 0.5f * (S.bx1[tid] + S.bx2[tid]);
    float cy = 0.5f * (S.by1[tid] + S.by2[tid]);
    float ext = fmaxf(S.bx2[tid] - S.bx1[tid], S.by2[tid] - S.by1[tid]);
    float rminx = real ? cx : 1e30f, rmaxx = real ? cx : -1e30f;
    float rminy = real ? cy : 1e30f, rmaxy = real ? cy : -1e30f;
    float rext  = real ? ext : 0.0f;
    rminx = wminf(rminx); rmaxx = wmaxf(rmaxx);
    rminy = wminf(rminy); rmaxy = wmaxf(rmaxy);
    rext  = wmaxf(rext);
    if (lane == 0) {
        S.warpred[wid][0] = rminx; S.warpred[wid][1] = rmaxx;
        S.warpred[wid][2] = rminy; S.warpred[wid][3] = rmaxy;
        S.warpred[wid][4] = rext;
    }
    __syncthreads();
    if (wid == 0) {
        float a0 = (lane < 16) ? S.warpred[lane][0] : 1e30f;
        float a1 = (lane < 16) ? S.warpred[lane][1] : -1e30f;
        float a2 = (lane < 16) ? S.warpred[lane][2] : 1e30f;
        float a3 = (lane < 16) ? S.warpred[lane][3] : -1e30f;
        float a4 = (lane < 16) ? S.warpred[lane][4] : 0.0f;
        a0 = wminf(a0); a1 = wmaxf(a1); a2 = wminf(a2); a3 = wmaxf(a3); a4 = wmaxf(a4);
        if (lane == 0) {
            S.red[0] = a0; S.red[1] = a1; S.red[2] = a2; S.red[3] = a3; S.red[4] = a4;
        }
    }
    __syncthreads();

    float minx = S.red[0], miny = S.red[2];
    float rx = S.red[1] - minx, ry = S.red[3] - miny;
    float cs = fmaxf(fmaxf(S.red[4], fmaxf(rx, ry) * (1.0f / 31.0f)), 1.0f) * 1.0001f;
    float inv_cs = 1.0f / cs;
    int ncx = min(32, (int)(rx * inv_cs) + 1);
    int ncy = min(32, (int)(ry * inv_cs) + 1);

    int cix = 0, ciy = 0;
    if (real) {
        cix = min(ncx - 1, max(0, (int)((cx - minx) * inv_cs)));
        ciy = min(ncy - 1, max(0, (int)((cy - miny) * inv_cs)));
        int cid = ciy * 32 + cix;
        S.cellid[tid] = (unsigned short)cid;
        atomicAdd(&S.cnt[cid], 1);
    }
    __syncthreads();

    {
        int c0 = S.cnt[2 * tid], c1 = S.cnt[2 * tid + 1];
        int s = c0 + c1;
        int incl = s;
        #pragma unroll
        for (int o = 1; o < 32; o <<= 1) {
            int n = __shfl_up_sync(0xFFFFFFFFu, incl, o);
            if (lane >= o) incl += n;
        }
        if (lane == 31) S.wtot[wid] = incl;
        __syncthreads();
        if (wid == 0) {
            int t = (lane < 16) ? S.wtot[lane] : 0;
            int ti = t;
            #pragma unroll
            for (int o = 1; o < 32; o <<= 1) {
                int n = __shfl_up_sync(0xFFFFFFFFu, ti, o);
                if (lane >= o) ti += n;
            }
            if (lane < 16) S.wtot[lane] = ti - t;
        }
        __syncthreads();
        int woff = S.wtot[wid];
        int excl = woff + incl - s;
        S.start[2 * tid] = excl;
        S.start[2 * tid + 1] = excl + c0;
    }
    __syncthreads();

    if (real) {
        int pos = atomicAdd(&S.start[S.cellid[tid]], 1);
        S.order[pos] = (unsigned short)tid;
    }
    __syncthreads();

    // sparse pair search: 3x3 neighbor cells, only j > i, set bit on IoU > 0.5
    if (real) {
        int i = tid;
        float ix1 = S.bx1[i], iy1 = S.by1[i], ix2 = S.bx2[i], iy2 = S.by2[i];
        float ai = S.ar[i];
        bool any = false;
        for (int dy = -1; dy <= 1; dy++) {
            int yy = ciy + dy;
            if (yy < 0 || yy >= ncy) continue;
            for (int dxl = -1; dxl <= 1; dxl++) {
                int xx = cix + dxl;
                if (xx < 0 || xx >= ncx) continue;
                int c = yy * 32 + xx;
                int e = S.start[c];
                int b = e - S.cnt[c];
                for (int k = b; k < e; k++) {
                    int j = S.order[k];
                    if (j <= i) continue;
                    float xx1 = fmaxf(ix1, S.bx1[j]);
                    float yy1 = fmaxf(iy1, S.by1[j]);
                    float xx2 = fminf(ix2, S.bx2[j]);
                    float yy2 = fminf(iy2, S.by2[j]);
                    float inter = fmaxf(xx2 - xx1, 0.0f) * fmaxf(yy2 - yy1, 0.0f);
                    if (3.0f * inter > ai + S.ar[j]) {
                        atomicOr(&S.sup[i][j >> 6], 1ull << (j & 63));
                        any = true;
                    }
                }
            }
        }
        if (any) atomicOr(&S.supmark[i >> 6], 1ull << (i & 63));
    }
    __syncthreads();

    // sparse greedy: visit only alive suppressor rows in index order (exact)
    if (tid == 0) {
        unsigned long long dropped[8] = {0,0,0,0,0,0,0,0};
        for (int w = 0; w < 8; w++) {
            unsigned long long rem = S.supmark[w] & S.keepw[w];
            while (true) {
                unsigned long long r2 = rem & ~dropped[w];
                if (!r2) break;
                int b = __ffsll((long long)r2) - 1;
                rem &= ~(1ull << b);
                int i = (w << 6) + b;
                #pragma unroll
                for (int w2 = 0; w2 < 8; w2++) dropped[w2] |= S.sup[i][w2];
            }
        }
        #pragma unroll
        for (int w = 0; w < 8; w++) S.keepw[w] &= ~dropped[w];
    }
    __syncthreads();

    int lev = (task < 112) ? 0 : ((task < 224) ? 1 : 2);
    int tt  = task - lev * 112;
    long long tbase = (long long)((lev * 16 + tt / 7) * 7 + tt % 7) * KTOP;
    float* okeep = out + 840000 + tbase;
    for (int r = tid; r < KTOP; r += 512)
        okeep[r] = ((S.keepw[r >> 6] >> (r & 63)) & 1ull) ? 1.0f : 0.0f;
    if (tid == 0) g_cnt[task] = 0;
}

// ---------------- launcher ----------------
extern "C" void kernel_launch(void* const* d_in, const int* in_sizes, int n_in,
                              void* d_out, int out_size) {
    const float *cls3 = nullptr, *cls4 = nullptr, *cls5 = nullptr;
    const float *reg3 = nullptr, *reg4 = nullptr, *reg5 = nullptr;
    for (int i = 0; i < n_in; i++) {
        switch (in_sizes[i]) {
            case 14155776: cls3 = (const float*)d_in[i]; break;
            case 7077888:  reg3 = (const float*)d_in[i]; break;
            case 3538944:  cls4 = (const float*)d_in[i]; break;
            case 1769472:  reg4 = (const float*)d_in[i]; break;
            case 884736:   cls5 = (const float*)d_in[i]; break;
            case 442368:   reg5 = (const float*)d_in[i]; break;
        }
    }
    float* out = (float*)d_out;
    cudaFuncSetAttribute(k_post, cudaFuncAttributeMaxDynamicSharedMemorySize,
                         (int)sizeof(PostSmem));
    k_scan<<<672, 512>>>(cls3, cls4, cls5);
    k_main<<<NTASK, 1024>>>(cls3, cls4, cls5, reg3, reg4, reg5, out);
    k_post<<<NTASK, 512, sizeof(PostSmem)>>>(out);
}

// round 13
// speedup vs baseline: 2.2255x; 1.3605x over previous
#include <cuda_runtime.h>
#include <cstdint>

#define KTOP 500
#define CAND_MAX 4096
#define NBIN 4096
#define NTASK 336
#define SCAN_BUF 2048
#define NTH 512

// ---------------- global scratch ----------------
__device__ unsigned long long g_cand[NTASK][CAND_MAX];
__device__ int g_cnt[NTASK];   // zero at load; restored by k_fused

__device__ __forceinline__ unsigned int mapf(float v) {
    unsigned int u = __float_as_uint(v);
    return (u & 0x80000000u) ? ~u : (u | 0x80000000u);
}
__device__ __forceinline__ float unmapf(unsigned int u) {
    return __uint_as_float((u & 0x80000000u) ? (u ^ 0x80000000u) : ~u);
}

__device__ __forceinline__ void task_info(int task, int& lev, int& img, int& cls,
                                          int& H, int& HW) {
    lev = (task < 112) ? 0 : ((task < 224) ? 1 : 2);
    int tt = task - lev * 112;
    img = tt / 7;
    cls = tt % 7;
    H = 192 >> lev;
    HW = H * H;
}

// ---------------- kernel 1: streaming compaction, smem-buffered ----------------
__global__ __launch_bounds__(512, 4) void k_scan(
    const float* __restrict__ cls3, const float* __restrict__ cls4,
    const float* __restrict__ cls5)
{
    __shared__ unsigned long long s_buf[SCAN_BUF];
    __shared__ int s_cnt, s_base;

    int b = blockIdx.x;
    int task, chunk, nchunk;
    if (b < 448)      { task = b >> 2;          chunk = b & 3; nchunk = 4; }
    else if (b < 560) { task = 112 + (b - 448); chunk = 0;     nchunk = 1; }
    else              { task = 224 + (b - 560); chunk = 0;     nchunk = 1; }

    int lev, img, cls, H, HW;
    task_info(task, lev, img, cls, H, HW);

    const float* clsP = (lev == 0) ? cls3 : ((lev == 1) ? cls4 : cls5);
    float thf = (lev == 0) ? -1.55f : ((lev == 1) ? -2.10f : -2.80f);

    if (threadIdx.x == 0) s_cnt = 0;
    __syncthreads();

    int nv4 = HW >> 2;
    int start = chunk * 512 + threadIdx.x;
    int stride = nchunk * 512;

    const float4* p0 = (const float4*)(clsP + (size_t)(img * 24 + 0 * 8 + cls + 1) * HW);
    const float4* p1 = (const float4*)(clsP + (size_t)(img * 24 + 1 * 8 + cls + 1) * HW);
    const float4* p2 = (const float4*)(clsP + (size_t)(img * 24 + 2 * 8 + cls + 1) * HW);

    for (int i4 = start; i4 < nv4; i4 += stride) {
        float4 v0 = p0[i4];
        float4 v1 = p1[i4];
        float4 v2 = p2[i4];
        #pragma unroll
        for (int a = 0; a < 3; a++) {
            float4 v = (a == 0) ? v0 : (a == 1) ? v1 : v2;
            #pragma unroll
            for (int e = 0; e < 4; e++) {
                float f = (e == 0) ? v.x : (e == 1) ? v.y : (e == 2) ? v.z : v.w;
                if (f > thf) {
                    int pos = atomicAdd(&s_cnt, 1);
                    if (pos < SCAN_BUF) {
                        unsigned n = (unsigned)((i4 * 4 + e) * 3 + a);
                        s_buf[pos] = ((unsigned long long)mapf(f) << 32)
                                   | (unsigned long long)(~n);
                    }
                }
            }
        }
    }
    __syncthreads();

    int scnt = s_cnt;
    if (threadIdx.x == 0) {
        int rep = (scnt > SCAN_BUF) ? scnt + 100000 : scnt;  // poison -> exact fallback
        s_base = atomicAdd(&g_cnt[task], rep);
    }
    __syncthreads();
    int base = s_base;
    int nf = min(scnt, SCAN_BUF);
    for (int i = threadIdx.x; i < nf; i += 512) {
        int p = base + i;
        if (p < CAND_MAX) g_cand[task][p] = s_buf[i];
    }
}

// ---------------- kernel 2: fused select/sort/decode + spatial-hash NMS ----------------
struct Fused {
    union {
        unsigned long long cand[CAND_MAX];                               // 32768 B
        struct { unsigned int hist[NBIN]; unsigned int scan[NTH]; } h;   // 18432 B
        unsigned long long sup[KTOP][8];                                 // 32000 B
    } big;
    float bx1[512], by1[512], bx2[512], by2[512], ar[512];
    int cellcnt[1024];
    int cellstart[1024];
    unsigned short order[512];
    unsigned short cellid[512];
    unsigned long long keepw[8];
    unsigned long long supmark[8];
    float warpred[16][5];
    float red[5];
    int wtot[16];
    int T, cntAbove, cnt_s;
};

__device__ void find_thr(Fused& S, int need, int tid, int& T_out, int& above_out) {
    int t8 = tid * 8;
    unsigned hh[8];
    unsigned sum = 0;
    #pragma unroll
    for (int e = 0; e < 8; e++) { hh[e] = S.big.h.hist[t8 + e]; sum += hh[e]; }
    S.big.h.scan[tid] = sum;
    __syncthreads();
    for (int off = 1; off < NTH; off <<= 1) {
        unsigned add = (tid + off < NTH) ? S.big.h.scan[tid + off] : 0u;
        __syncthreads();
        S.big.h.scan[tid] += add;
        __syncthreads();
    }
    unsigned sfx = S.big.h.scan[tid];
    unsigned nxt = (tid < NTH - 1) ? S.big.h.scan[tid + 1] : 0u;
    if (sfx >= (unsigned)need && nxt < (unsigned)need) {
        unsigned c = nxt;
        for (int b = 7; b >= 0; b--) {
            if (c + hh[b] >= (unsigned)need) { S.T = t8 + b; S.cntAbove = (int)c; break; }
            c += hh[b];
        }
    }
    __syncthreads();
    T_out = S.T;
    above_out = S.cntAbove;
}

__device__ __forceinline__ float wmaxf(float v) {
    #pragma unroll
    for (int o = 16; o; o >>= 1) v = fmaxf(v, __shfl_xor_sync(0xFFFFFFFFu, v, o));
    return v;
}
__device__ __forceinline__ float wminf(float v) {
    #pragma unroll
    for (int o = 16; o; o >>= 1) v = fminf(v, __shfl_xor_sync(0xFFFFFFFFu, v, o));
    return v;
}

__global__ __launch_bounds__(NTH, 4) void k_fused(
    const float* __restrict__ cls3, const float* __restrict__ cls4, const float* __restrict__ cls5,
    const float* __restrict__ reg3, const float* __restrict__ reg4, const float* __restrict__ reg5,
    float* __restrict__ out)
{
    extern __shared__ unsigned char sraw[];
    Fused& S = *reinterpret_cast<Fused*>(sraw);
    const int tid = threadIdx.x;
    const int lane = tid & 31;
    const int wid = tid >> 5;

    int task = blockIdx.x;
    int lev, img, cls, H, HW;
    task_info(task, lev, img, cls, H, HW);
    const int W = H;
    const float stride = (float)(8 << lev);
    const float asize  = (float)(16 << lev);

    const float* clsP = (lev == 0) ? cls3 : ((lev == 1) ? cls4 : cls5);
    const float* regP = (lev == 0) ? reg3 : ((lev == 1) ? reg4 : reg5);
    const float* plane0 = clsP + (size_t)(img * 24 + 0 * 8 + cls + 1) * HW;
    const float* plane1 = clsP + (size_t)(img * 24 + 1 * 8 + cls + 1) * HW;
    const float* plane2 = clsP + (size_t)(img * 24 + 2 * 8 + cls + 1) * HW;
    const float* planes[3] = { plane0, plane1, plane2 };

    if (tid < 8) { S.keepw[tid] = 0ull; S.supmark[tid] = 0ull; }

    int cnt = g_cnt[task];

    if (cnt >= KTOP && cnt <= CAND_MAX) {
        for (int i = tid; i < cnt; i += NTH) S.big.cand[i] = g_cand[task][i];
        __syncthreads();
    } else {
        // exact fallback: 12-bit histogram select over raw planes
        for (int i = tid; i < NBIN; i += NTH) S.big.h.hist[i] = 0;
        __syncthreads();
        for (int a = 0; a < 3; a++) {
            const float* p = planes[a];
            for (int i = tid; i < HW; i += NTH) {
                unsigned u = mapf(p[i]);
                int bin = (int)(u >> 20);
                unsigned m = __match_any_sync(__activemask(), bin);
                int leader = __ffs(m) - 1;
                if (lane == leader) atomicAdd(&S.big.h.hist[bin], (unsigned)__popc(m));
            }
        }
        __syncthreads();
        int T, above;
        find_thr(S, KTOP, tid, T, above);
        if (tid == 0) S.cnt_s = 0;
        __syncthreads();
        for (int a = 0; a < 3; a++) {
            const float* p = planes[a];
            for (int i = tid; i < HW; i += NTH) {
                unsigned u = mapf(p[i]);
                if ((int)(u >> 20) >= T) {
                    int pos = atomicAdd(&S.cnt_s, 1);
                    if (pos < CAND_MAX) {
                        unsigned n = (unsigned)(i * 3 + a);
                        S.big.cand[pos] = ((unsigned long long)u << 32) | (unsigned long long)(~n);
                    }
                }
            }
        }
        __syncthreads();
        cnt = S.cnt_s;

        if (cnt > CAND_MAX) {
            for (int i = tid; i < NBIN; i += NTH) S.big.h.hist[i] = 0;
            __syncthreads();
            for (int a = 0; a < 3; a++) {
                const float* p = planes[a];
                for (int i = tid; i < HW; i += NTH) {
                    unsigned u = mapf(p[i]);
                    if ((int)(u >> 20) == T)
                        atomicAdd(&S.big.h.hist[(u >> 8) & 0xFFFu], 1u);
                }
            }
            __syncthreads();
            int T2, ab2;
            find_thr(S, KTOP - above, tid, T2, ab2);
            if (tid == 0) S.cnt_s = 0;
            __syncthreads();
            for (int a = 0; a < 3; a++) {
                const float* p = planes[a];
                for (int i = tid; i < HW; i += NTH) {
                    unsigned u = mapf(p[i]);
                    int bin = (int)(u >> 20);
                    if (bin > T || (bin == T && (int)((u >> 8) & 0xFFFu) >= T2)) {
                        int pos = atomicAdd(&S.cnt_s, 1);
                        if (pos < CAND_MAX) {
                            unsigned n = (unsigned)(i * 3 + a);
                            S.big.cand[pos] = ((unsigned long long)u << 32) | (unsigned long long)(~n);
                        }
                    }
                }
            }
            __syncthreads();
            cnt = S.cnt_s;
        }
        if (cnt > CAND_MAX) cnt = CAND_MAX;
    }

    // ---------- smem bitonic sort (descending), pad to M ----------
    {
        int M = 512;
        while (M < cnt) M <<= 1;
        for (int i = cnt + tid; i < M; i += NTH) S.big.cand[i] = 0ull;
        __syncthreads();
        for (int k = 2; k <= M; k <<= 1) {
            for (int j = k >> 1; j > 0; j >>= 1) {
                if (j >= 16) __syncthreads(); else __syncwarp();
                for (int i = tid; i < M; i += NTH) {
                    int ixj = i ^ j;
                    if (ixj > i) {
                        unsigned long long a = S.big.cand[i], b = S.big.cand[ixj];
                        bool sw = ((i & k) == 0) ? (a < b) : (a > b);
                        if (sw) { S.big.cand[i] = b; S.big.cand[ixj] = a; }
                    }
                }
            }
        }
        __syncthreads();
    }

    // ---------- decode top-500, write boxes/scores/labels, stash in smem ----------
    long long tbase = (long long)((lev * 16 + img) * 7 + cls) * KTOP;
    float4* obox4 = (float4*)(out + tbase * 4);
    float* osc   = out + 672000 + tbase;
    float* olab  = out + 1008000 + tbase;

    {
        int r = tid;
        bool valid_bit = false;
        float bx1v = 0.0f, by1v = 0.0f, bx2v = 0.0f, by2v = 0.0f;
        if (r < KTOP) {
            unsigned long long key = S.big.cand[r];
            unsigned u = (unsigned)(key >> 32);
            unsigned n = ~((unsigned)key);
            float logit = unmapf(u);
            float score = __fdividef(1.0f, 1.0f + __expf(-logit));

            int a = (int)(n % 3u);
            int p = (int)(n / 3u);
            int x = p % W;
            int y = p / W;
            float sqv = (a == 0) ? 0.70710678118654752f : ((a == 1) ? 1.0f : 1.41421356237309505f);
            float wa = asize * sqv;
            float ha = asize / sqv;
            float cxa = ((float)x + 0.5f) * stride;
            float cya = ((float)y + 0.5f) * stride;

            size_t rb = (size_t)(img * 12 + a * 4) * HW + (size_t)p;
            float dx = regP[rb];
            float dy = regP[rb + HW];
            float dw = regP[rb + 2 * (size_t)HW];
            float dh = regP[rb + 3 * (size_t)HW];

            float cx = dx * wa + cxa;
            float cy = dy * ha + cya;
            float bw = __expf(dw) * wa;
            float bh = __expf(dh) * ha;
            bx1v = cx - 0.5f * bw; by1v = cy - 0.5f * bh;
            bx2v = cx + 0.5f * bw; by2v = cy + 0.5f * bh;

            obox4[r] = make_float4(bx1v, by1v, bx2v, by2v);
            osc[r] = score;
            olab[r] = (float)cls;
            valid_bit = (score > 0.05f);
        }
        unsigned b = __ballot_sync(0xFFFFFFFFu, valid_bit);
        if (lane == 0 && b)
            atomicOr(&S.keepw[tid >> 6], (unsigned long long)b << ((tid >> 5 & 1) * 32));
        __syncthreads();   // all cand reads done before sup (aliased) is zeroed below
        S.bx1[tid] = bx1v; S.by1[tid] = by1v; S.bx2[tid] = bx2v; S.by2[tid] = by2v;
        S.ar[tid]  = (bx2v - bx1v) * (by2v - by1v);
    }

    // ---------- zero sup matrix (reuses cand region) + hash init ----------
    for (int i = tid; i < KTOP * 8; i += NTH)
        (&S.big.sup[0][0])[i] = 0ull;
    for (int i = tid; i < 1024; i += NTH) S.cellcnt[i] = 0;
    __syncthreads();

    // ---------- spatial hash build ----------
    bool real = (tid < KTOP);
    float cx = 0.5f * (S.bx1[tid] + S.bx2[tid]);
    float cy = 0.5f * (S.by1[tid] + S.by2[tid]);
    float ext = fmaxf(S.bx2[tid] - S.bx1[tid], S.by2[tid] - S.by1[tid]);
    float rminx = real ? cx : 1e30f, rmaxx = real ? cx : -1e30f;
    float rminy = real ? cy : 1e30f, rmaxy = real ? cy : -1e30f;
    float rext  = real ? ext : 0.0f;
    rminx = wminf(rminx); rmaxx = wmaxf(rmaxx);
    rminy = wminf(rminy); rmaxy = wmaxf(rmaxy);
    rext  = wmaxf(rext);
    if (lane == 0) {
        S.warpred[wid][0] = rminx; S.warpred[wid][1] = rmaxx;
        S.warpred[wid][2] = rminy; S.warpred[wid][3] = rmaxy;
        S.warpred[wid][4] = rext;
    }
    __syncthreads();
    if (wid == 0) {
        float a0 = (lane < 16) ? S.warpred[lane][0] : 1e30f;
        float a1 = (lane < 16) ? S.warpred[lane][1] : -1e30f;
        float a2 = (lane < 16) ? S.warpred[lane][2] : 1e30f;
        float a3 = (lane < 16) ? S.warpred[lane][3] : -1e30f;
        float a4 = (lane < 16) ? S.warpred[lane][4] : 0.0f;
        a0 = wminf(a0); a1 = wmaxf(a1); a2 = wminf(a2); a3 = wmaxf(a3); a4 = wmaxf(a4);
        if (lane == 0) {
            S.red[0] = a0; S.red[1] = a1; S.red[2] = a2; S.red[3] = a3; S.red[4] = a4;
        }
    }
    __syncthreads();

    float minx = S.red[0], miny = S.red[2];
    float rx = S.red[1] - minx, ry = S.red[3] - miny;
    float cs = fmaxf(fmaxf(S.red[4], fmaxf(rx, ry) * (1.0f / 31.0f)), 1.0f) * 1.0001f;
    float inv_cs = 1.0f / cs;
    int ncx = min(32, (int)(rx * inv_cs) + 1);
    int ncy = min(32, (int)(ry * inv_cs) + 1);

    int cix = 0, ciy = 0;
    if (real) {
        cix = min(ncx - 1, max(0, (int)((cx - minx) * inv_cs)));
        ciy = min(ncy - 1, max(0, (int)((cy - miny) * inv_cs)));
        int cid = ciy * 32 + cix;
        S.cellid[tid] = (unsigned short)cid;
        atomicAdd(&S.cellcnt[cid], 1);
    }
    __syncthreads();

    // exclusive scan of 1024 cell counts (512 threads x 2)
    {
        int c0 = S.cellcnt[2 * tid], c1 = S.cellcnt[2 * tid + 1];
        int s = c0 + c1;
        int incl = s;
        #pragma unroll
        for (int o = 1; o < 32; o <<= 1) {
            int n = __shfl_up_sync(0xFFFFFFFFu, incl, o);
            if (lane >= o) incl += n;
        }
        if (lane == 31) S.wtot[wid] = incl;
        __syncthreads();
        if (wid == 0) {
            int t = (lane < 16) ? S.wtot[lane] : 0;
            int ti = t;
            #pragma unroll
            for (int o = 1; o < 32; o <<= 1) {
                int n = __shfl_up_sync(0xFFFFFFFFu, ti, o);
                if (lane >= o) ti += n;
            }
            if (lane < 16) S.wtot[lane] = ti - t;
        }
        __syncthreads();
        int woff = S.wtot[wid];
        int excl = woff + incl - s;
        S.cellstart[2 * tid] = excl;
        S.cellstart[2 * tid + 1] = excl + c0;
    }
    __syncthreads();

    if (real) {
        int pos = atomicAdd(&S.cellstart[S.cellid[tid]], 1);
        S.order[pos] = (unsigned short)tid;
    }
    __syncthreads();

    // sparse pair search: 3x3 neighbor cells, only j > i, set bit on IoU > 0.5
    if (real) {
        int i = tid;
        float ix1 = S.bx1[i], iy1 = S.by1[i], ix2 = S.bx2[i], iy2 = S.by2[i];
        float ai = S.ar[i];
        bool any = false;
        for (int dy = -1; dy <= 1; dy++) {
            int yy = ciy + dy;
            if (yy < 0 || yy >= ncy) continue;
            for (int dxl = -1; dxl <= 1; dxl++) {
                int xx = cix + dxl;
                if (xx < 0 || xx >= ncx) continue;
                int c = yy * 32 + xx;
                int e = S.cellstart[c];
                int b = e - S.cellcnt[c];
                for (int k = b; k < e; k++) {
                    int j = S.order[k];
                    if (j <= i) continue;
                    float xx1 = fmaxf(ix1, S.bx1[j]);
                    float yy1 = fmaxf(iy1, S.by1[j]);
                    float xx2 = fminf(ix2, S.bx2[j]);
                    float yy2 = fminf(iy2, S.by2[j]);
                    float inter = fmaxf(xx2 - xx1, 0.0f) * fmaxf(yy2 - yy1, 0.0f);
                    if (3.0f * inter > ai + S.ar[j]) {
                        atomicOr(&S.big.sup[i][j >> 6], 1ull << (j & 63));
                        any = true;
                    }
                }
            }
        }
        if (any) atomicOr(&S.supmark[i >> 6], 1ull << (i & 63));
    }
    __syncthreads();

    // sparse greedy: visit only alive suppressor rows in index order (exact)
    if (tid == 0) {
        unsigned long long dropped[8] = {0,0,0,0,0,0,0,0};
        for (int w = 0; w < 8; w++) {
            unsigned long long rem = S.supmark[w] & S.keepw[w];
            while (true) {
                unsigned long long r2 = rem & ~dropped[w];
                if (!r2) break;
                int b = __ffsll((long long)r2) - 1;
                rem &= ~(1ull << b);
                int i = (w << 6) + b;
                #pragma unroll
                for (int w2 = 0; w2 < 8; w2++) dropped[w2] |= S.big.sup[i][w2];
            }
        }
        #pragma unroll
        for (int w = 0; w < 8; w++) S.keepw[w] &= ~dropped[w];
    }
    __syncthreads();

    float* okeep = out + 840000 + tbase;
    for (int r = tid; r < KTOP; r += NTH)
        okeep[r] = ((S.keepw[r >> 6] >> (r & 63)) & 1ull) ? 1.0f : 0.0f;
    if (tid == 0) g_cnt[task] = 0;   // restore invariant for next graph replay
}

// ---------------- launcher ----------------
extern "C" void kernel_launch(void* const* d_in, const int* in_sizes, int n_in,
                              void* d_out, int out_size) {
    const float *cls3 = nullptr, *cls4 = nullptr, *cls5 = nullptr;
    const float *reg3 = nullptr, *reg4 = nullptr, *reg5 = nullptr;
    for (int i = 0; i < n_in; i++) {
        switch (in_sizes[i]) {
            case 14155776: cls3 = (const float*)d_in[i]; break;
            case 7077888:  reg3 = (const float*)d_in[i]; break;
            case 3538944:  cls4 = (const float*)d_in[i]; break;
            case 1769472:  reg4 = (const float*)d_in[i]; break;
            case 884736:   cls5 = (const float*)d_in[i]; break;
            case 442368:   reg5 = (const float*)d_in[i]; break;
        }
    }
    float* out = (float*)d_out;
    cudaFuncSetAttribute(k_fused, cudaFuncAttributeMaxDynamicSharedMemorySize,
                         (int)sizeof(Fused));
    k_scan<<<672, 512>>>(cls3, cls4, cls5);
    k_fused<<<NTASK, NTH, sizeof(Fused)>>>(cls3, cls4, cls5, reg3, reg4, reg5, out);
}

// round 14
// speedup vs baseline: 2.9891x; 1.3432x over previous
#include <cuda_runtime.h>
#include <cstdint>

#define KTOP 500
#define CAND_MAX 4096
#define NBIN 4096
#define NTASK 336
#define SCAN_BUF 2048
#define NTH 512

// ---------------- global scratch ----------------
__device__ unsigned long long g_cand[NTASK][CAND_MAX];
__device__ int g_cnt[NTASK];   // zero at load; restored by k_fused

__device__ __forceinline__ unsigned int mapf(float v) {
    unsigned int u = __float_as_uint(v);
    return (u & 0x80000000u) ? ~u : (u | 0x80000000u);
}
__device__ __forceinline__ float unmapf(unsigned int u) {
    return __uint_as_float((u & 0x80000000u) ? (u ^ 0x80000000u) : ~u);
}

__device__ __forceinline__ void task_info(int task, int& lev, int& img, int& cls,
                                          int& H, int& HW) {
    lev = (task < 112) ? 0 : ((task < 224) ? 1 : 2);
    int tt = task - lev * 112;
    img = tt / 7;
    cls = tt % 7;
    H = 192 >> lev;
    HW = H * H;
}

// ---------------- kernel 1: streaming compaction, smem-buffered ----------------
__global__ __launch_bounds__(512, 4) void k_scan(
    const float* __restrict__ cls3, const float* __restrict__ cls4,
    const float* __restrict__ cls5)
{
    __shared__ unsigned long long s_buf[SCAN_BUF];
    __shared__ int s_cnt, s_base;

    int b = blockIdx.x;
    int task, chunk, nchunk;
    if (b < 448)      { task = b >> 2;          chunk = b & 3; nchunk = 4; }
    else if (b < 560) { task = 112 + (b - 448); chunk = 0;     nchunk = 1; }
    else              { task = 224 + (b - 560); chunk = 0;     nchunk = 1; }

    int lev, img, cls, H, HW;
    task_info(task, lev, img, cls, H, HW);

    const float* clsP = (lev == 0) ? cls3 : ((lev == 1) ? cls4 : cls5);
    float thf = (lev == 0) ? -1.55f : ((lev == 1) ? -2.10f : -2.80f);

    if (threadIdx.x == 0) s_cnt = 0;
    __syncthreads();

    int nv4 = HW >> 2;
    int start = chunk * 512 + threadIdx.x;
    int stride = nchunk * 512;

    const float4* p0 = (const float4*)(clsP + (size_t)(img * 24 + 0 * 8 + cls + 1) * HW);
    const float4* p1 = (const float4*)(clsP + (size_t)(img * 24 + 1 * 8 + cls + 1) * HW);
    const float4* p2 = (const float4*)(clsP + (size_t)(img * 24 + 2 * 8 + cls + 1) * HW);

    for (int i4 = start; i4 < nv4; i4 += stride) {
        float4 v0 = p0[i4];
        float4 v1 = p1[i4];
        float4 v2 = p2[i4];
        #pragma unroll
        for (int a = 0; a < 3; a++) {
            float4 v = (a == 0) ? v0 : (a == 1) ? v1 : v2;
            #pragma unroll
            for (int e = 0; e < 4; e++) {
                float f = (e == 0) ? v.x : (e == 1) ? v.y : (e == 2) ? v.z : v.w;
                if (f > thf) {
                    int pos = atomicAdd(&s_cnt, 1);
                    if (pos < SCAN_BUF) {
                        unsigned n = (unsigned)((i4 * 4 + e) * 3 + a);
                        s_buf[pos] = ((unsigned long long)mapf(f) << 32)
                                   | (unsigned long long)(~n);
                    }
                }
            }
        }
    }
    __syncthreads();

    int scnt = s_cnt;
    if (threadIdx.x == 0) {
        int rep = (scnt > SCAN_BUF) ? scnt + 100000 : scnt;  // poison -> exact fallback
        s_base = atomicAdd(&g_cnt[task], rep);
    }
    __syncthreads();
    int base = s_base;
    int nf = min(scnt, SCAN_BUF);
    for (int i = threadIdx.x; i < nf; i += 512) {
        int p = base + i;
        if (p < CAND_MAX) g_cand[task][p] = s_buf[i];
    }
}

// ---------------- kernel 2: fused select/sort/decode + spatial-hash NMS ----------------
struct Fused {
    union {
        unsigned long long cand[CAND_MAX];                               // 32768 B
        struct { unsigned int hist[NBIN]; unsigned int scan[NTH]; } h;   // 18432 B
        unsigned long long sup[KTOP][8];                                 // 32000 B
    } big;
    float bx1[512], by1[512], bx2[512], by2[512], ar[512];
    int cellcnt[1024];
    int cellstart[1024];
    unsigned short order[512];
    unsigned short cellid[512];
    unsigned long long keepw[8];
    unsigned long long supmark[8];
    float warpred[16][5];
    float red[5];
    int wtot[16];
    int T, cntAbove, cnt_s;
};

__device__ void find_thr(Fused& S, int need, int tid, int& T_out, int& above_out) {
    int t8 = tid * 8;
    unsigned hh[8];
    unsigned sum = 0;
    #pragma unroll
    for (int e = 0; e < 8; e++) { hh[e] = S.big.h.hist[t8 + e]; sum += hh[e]; }
    S.big.h.scan[tid] = sum;
    __syncthreads();
    for (int off = 1; off < NTH; off <<= 1) {
        unsigned add = (tid + off < NTH) ? S.big.h.scan[tid + off] : 0u;
        __syncthreads();
        S.big.h.scan[tid] += add;
        __syncthreads();
    }
    unsigned sfx = S.big.h.scan[tid];
    unsigned nxt = (tid < NTH - 1) ? S.big.h.scan[tid + 1] : 0u;
    if (sfx >= (unsigned)need && nxt < (unsigned)need) {
        unsigned c = nxt;
        for (int b = 7; b >= 0; b--) {
            if (c + hh[b] >= (unsigned)need) { S.T = t8 + b; S.cntAbove = (int)c; break; }
            c += hh[b];
        }
    }
    __syncthreads();
    T_out = S.T;
    above_out = S.cntAbove;
}

__device__ __forceinline__ float wmaxf(float v) {
    #pragma unroll
    for (int o = 16; o; o >>= 1) v = fmaxf(v, __shfl_xor_sync(0xFFFFFFFFu, v, o));
    return v;
}
__device__ __forceinline__ float wminf(float v) {
    #pragma unroll
    for (int o = 16; o; o >>= 1) v = fminf(v, __shfl_xor_sync(0xFFFFFFFFu, v, o));
    return v;
}

__global__ __launch_bounds__(NTH, 4) void k_fused(
    const float* __restrict__ cls3, const float* __restrict__ cls4, const float* __restrict__ cls5,
    const float* __restrict__ reg3, const float* __restrict__ reg4, const float* __restrict__ reg5,
    float* __restrict__ out)
{
    extern __shared__ unsigned char sraw[];
    Fused& S = *reinterpret_cast<Fused*>(sraw);
    const int tid = threadIdx.x;
    const int lane = tid & 31;
    const int wid = tid >> 5;

    int task = blockIdx.x;
    int lev, img, cls, H, HW;
    task_info(task, lev, img, cls, H, HW);
    const int W = H;
    const float stride = (float)(8 << lev);
    const float asize  = (float)(16 << lev);

    const float* clsP = (lev == 0) ? cls3 : ((lev == 1) ? cls4 : cls5);
    const float* regP = (lev == 0) ? reg3 : ((lev == 1) ? reg4 : reg5);
    const float* plane0 = clsP + (size_t)(img * 24 + 0 * 8 + cls + 1) * HW;
    const float* plane1 = clsP + (size_t)(img * 24 + 1 * 8 + cls + 1) * HW;
    const float* plane2 = clsP + (size_t)(img * 24 + 2 * 8 + cls + 1) * HW;
    const float* planes[3] = { plane0, plane1, plane2 };

    if (tid < 8) { S.keepw[tid] = 0ull; S.supmark[tid] = 0ull; }

    int cnt = g_cnt[task];

    if (cnt >= KTOP && cnt <= CAND_MAX) {
        for (int i = tid; i < cnt; i += NTH) S.big.cand[i] = g_cand[task][i];
        __syncthreads();
    } else {
        // exact fallback: 12-bit histogram select over raw planes
        for (int i = tid; i < NBIN; i += NTH) S.big.h.hist[i] = 0;
        __syncthreads();
        for (int a = 0; a < 3; a++) {
            const float* p = planes[a];
            for (int i = tid; i < HW; i += NTH) {
                unsigned u = mapf(p[i]);
                int bin = (int)(u >> 20);
                unsigned m = __match_any_sync(__activemask(), bin);
                int leader = __ffs(m) - 1;
                if (lane == leader) atomicAdd(&S.big.h.hist[bin], (unsigned)__popc(m));
            }
        }
        __syncthreads();
        int T, above;
        find_thr(S, KTOP, tid, T, above);
        if (tid == 0) S.cnt_s = 0;
        __syncthreads();
        for (int a = 0; a < 3; a++) {
            const float* p = planes[a];
            for (int i = tid; i < HW; i += NTH) {
                unsigned u = mapf(p[i]);
                if ((int)(u >> 20) >= T) {
                    int pos = atomicAdd(&S.cnt_s, 1);
                    if (pos < CAND_MAX) {
                        unsigned n = (unsigned)(i * 3 + a);
                        S.big.cand[pos] = ((unsigned long long)u << 32) | (unsigned long long)(~n);
                    }
                }
            }
        }
        __syncthreads();
        cnt = S.cnt_s;

        if (cnt > CAND_MAX) {
            for (int i = tid; i < NBIN; i += NTH) S.big.h.hist[i] = 0;
            __syncthreads();
            for (int a = 0; a < 3; a++) {
                const float* p = planes[a];
                for (int i = tid; i < HW; i += NTH) {
                    unsigned u = mapf(p[i]);
                    if ((int)(u >> 20) == T)
                        atomicAdd(&S.big.h.hist[(u >> 8) & 0xFFFu], 1u);
                }
            }
            __syncthreads();
            int T2, ab2;
            find_thr(S, KTOP - above, tid, T2, ab2);
            if (tid == 0) S.cnt_s = 0;
            __syncthreads();
            for (int a = 0; a < 3; a++) {
                const float* p = planes[a];
                for (int i = tid; i < HW; i += NTH) {
                    unsigned u = mapf(p[i]);
                    int bin = (int)(u >> 20);
                    if (bin > T || (bin == T && (int)((u >> 8) & 0xFFFu) >= T2)) {
                        int pos = atomicAdd(&S.cnt_s, 1);
                        if (pos < CAND_MAX) {
                            unsigned n = (unsigned)(i * 3 + a);
                            S.big.cand[pos] = ((unsigned long long)u << 32) | (unsigned long long)(~n);
                        }
                    }
                }
            }
            __syncthreads();
            cnt = S.cnt_s;
        }
        if (cnt > CAND_MAX) cnt = CAND_MAX;
    }

    // ---------- sort descending ----------
    if (cnt <= 1024) {
        // hybrid bitonic: 2 elems/thread in regs; j>=64 via smem (10 stages),
        // j==32 in-thread, j<=16 via shfl. Global rule desc = ((i & k) == 0).
        for (int i = cnt + tid; i < 1024; i += NTH) S.big.cand[i] = 0ull;
        __syncthreads();

        const int base = wid << 6;
        const int i_lo = base + lane;
        const int i_hi = base + lane + 32;
        unsigned long long vlo = S.big.cand[i_lo];
        unsigned long long vhi = S.big.cand[i_hi];

        #define SHFL_STEP(k, j) do {                                               \
            unsigned long long plo = __shfl_xor_sync(0xFFFFFFFFu, vlo, (j));       \
            unsigned long long phi = __shfl_xor_sync(0xFFFFFFFFu, vhi, (j));       \
            bool low = ((lane & (j)) == 0);                                        \
            bool wl = (low == ((i_lo & (k)) == 0));                                \
            bool wh = (low == ((i_hi & (k)) == 0));                                \
            vlo = wl ? (vlo > plo ? vlo : plo) : (vlo < plo ? vlo : plo);          \
            vhi = wh ? (vhi > phi ? vhi : phi) : (vhi < phi ? vhi : phi);          \
        } while (0)

        #define INTHREAD_STEP(k) do {                                              \
            bool desc = ((i_lo & (k)) == 0);                                       \
            bool sw = desc ? (vlo < vhi) : (vlo > vhi);                            \
            if (sw) { unsigned long long t = vlo; vlo = vhi; vhi = t; }            \
        } while (0)

        // k = 2..32: pure shfl
        #pragma unroll
        for (int k = 2; k <= 32; k <<= 1) {
            #pragma unroll
            for (int j = k >> 1; j >= 1; j >>= 1) SHFL_STEP(k, j);
        }
        // k = 64
        INTHREAD_STEP(64);
        #pragma unroll
        for (int j = 16; j >= 1; j >>= 1) SHFL_STEP(64, j);

        // merge k = 128..1024
        #pragma unroll
        for (int k = 128; k <= 1024; k <<= 1) {
            S.big.cand[i_lo] = vlo;
            S.big.cand[i_hi] = vhi;
            for (int j = k >> 1; j >= 64; j >>= 1) {
                __syncthreads();
                #pragma unroll
                for (int t2 = 0; t2 < 2; t2++) {
                    int i = tid + t2 * 512;
                    int ixj = i ^ j;
                    if (ixj > i) {
                        unsigned long long a = S.big.cand[i], b = S.big.cand[ixj];
                        bool sw = ((i & k) == 0) ? (a < b) : (a > b);
                        if (sw) { S.big.cand[i] = b; S.big.cand[ixj] = a; }
                    }
                }
            }
            __syncthreads();
            vlo = S.big.cand[i_lo];
            vhi = S.big.cand[i_hi];
            INTHREAD_STEP(k);
            #pragma unroll
            for (int j = 16; j >= 1; j >>= 1) SHFL_STEP(k, j);
        }
        S.big.cand[i_lo] = vlo;
        S.big.cand[i_hi] = vhi;
        __syncthreads();
        #undef SHFL_STEP
        #undef INTHREAD_STEP
    } else {
        // generic smem bitonic for cnt in (1024, 4096]
        int M = 2048;
        while (M < cnt) M <<= 1;
        for (int i = cnt + tid; i < M; i += NTH) S.big.cand[i] = 0ull;
        __syncthreads();
        for (int k = 2; k <= M; k <<= 1) {
            for (int j = k >> 1; j > 0; j >>= 1) {
                for (int i = tid; i < M; i += NTH) {
                    int ixj = i ^ j;
                    if (ixj > i) {
                        unsigned long long a = S.big.cand[i], b = S.big.cand[ixj];
                        bool sw = ((i & k) == 0) ? (a < b) : (a > b);
                        if (sw) { S.big.cand[i] = b; S.big.cand[ixj] = a; }
                    }
                }
                __syncthreads();
            }
        }
    }

    // ---------- decode top-500, write boxes/scores/labels, stash in smem ----------
    long long tbase = (long long)((lev * 16 + img) * 7 + cls) * KTOP;
    float4* obox4 = (float4*)(out + tbase * 4);
    float* osc   = out + 672000 + tbase;
    float* olab  = out + 1008000 + tbase;

    {
        int r = tid;
        bool valid_bit = false;
        float bx1v = 0.0f, by1v = 0.0f, bx2v = 0.0f, by2v = 0.0f;
        if (r < KTOP) {
            unsigned long long key = S.big.cand[r];
            unsigned u = (unsigned)(key >> 32);
            unsigned n = ~((unsigned)key);
            float logit = unmapf(u);
            float score = __fdividef(1.0f, 1.0f + __expf(-logit));

            int a = (int)(n % 3u);
            int p = (int)(n / 3u);
            int x = p % W;
            int y = p / W;
            float sqv = (a == 0) ? 0.70710678118654752f : ((a == 1) ? 1.0f : 1.41421356237309505f);
            float wa = asize * sqv;
            float ha = asize / sqv;
            float cxa = ((float)x + 0.5f) * stride;
            float cya = ((float)y + 0.5f) * stride;

            size_t rb = (size_t)(img * 12 + a * 4) * HW + (size_t)p;
            float dx = regP[rb];
            float dy = regP[rb + HW];
            float dw = regP[rb + 2 * (size_t)HW];
            float dh = regP[rb + 3 * (size_t)HW];

            float cx = dx * wa + cxa;
            float cy = dy * ha + cya;
            float bw = __expf(dw) * wa;
            float bh = __expf(dh) * ha;
            bx1v = cx - 0.5f * bw; by1v = cy - 0.5f * bh;
            bx2v = cx + 0.5f * bw; by2v = cy + 0.5f * bh;

            obox4[r] = make_float4(bx1v, by1v, bx2v, by2v);
            osc[r] = score;
            olab[r] = (float)cls;
            valid_bit = (score > 0.05f);
        }
        unsigned b = __ballot_sync(0xFFFFFFFFu, valid_bit);
        if (lane == 0 && b)
            atomicOr(&S.keepw[tid >> 6], (unsigned long long)b << ((tid >> 5 & 1) * 32));
        __syncthreads();   // all cand reads done before sup (aliased) is zeroed below
        S.bx1[tid] = bx1v; S.by1[tid] = by1v; S.bx2[tid] = bx2v; S.by2[tid] = by2v;
        S.ar[tid]  = (bx2v - bx1v) * (by2v - by1v);
    }

    // ---------- zero sup matrix (reuses cand region) + hash init ----------
    for (int i = tid; i < KTOP * 8; i += NTH)
        (&S.big.sup[0][0])[i] = 0ull;
    for (int i = tid; i < 1024; i += NTH) S.cellcnt[i] = 0;
    __syncthreads();

    // ---------- spatial hash build ----------
    bool real = (tid < KTOP);
    float cx = 0.5f * (S.bx1[tid] + S.bx2[tid]);
    float cy = 0.5f * (S.by1[tid] + S.by2[tid]);
    float ext = fmaxf(S.bx2[tid] - S.bx1[tid], S.by2[tid] - S.by1[tid]);
    float rminx = real ? cx : 1e30f, rmaxx = real ? cx : -1e30f;
    float rminy = real ? cy : 1e30f, rmaxy = real ? cy : -1e30f;
    float rext  = real ? ext : 0.0f;
    rminx = wminf(rminx); rmaxx = wmaxf(rmaxx);
    rminy = wminf(rminy); rmaxy = wmaxf(rmaxy);
    rext  = wmaxf(rext);
    if (lane == 0) {
        S.warpred[wid][0] = rminx; S.warpred[wid][1] = rmaxx;
        S.warpred[wid][2] = rminy; S.warpred[wid][3] = rmaxy;
        S.warpred[wid][4] = rext;
    }
    __syncthreads();
    if (wid == 0) {
        float a0 = (lane < 16) ? S.warpred[lane][0] : 1e30f;
        float a1 = (lane < 16) ? S.warpred[lane][1] : -1e30f;
        float a2 = (lane < 16) ? S.warpred[lane][2] : 1e30f;
        float a3 = (lane < 16) ? S.warpred[lane][3] : -1e30f;
        float a4 = (lane < 16) ? S.warpred[lane][4] : 0.0f;
        a0 = wminf(a0); a1 = wmaxf(a1); a2 = wminf(a2); a3 = wmaxf(a3); a4 = wmaxf(a4);
        if (lane == 0) {
            S.red[0] = a0; S.red[1] = a1; S.red[2] = a2; S.red[3] = a3; S.red[4] = a4;
        }
    }
    __syncthreads();

    float minx = S.red[0], miny = S.red[2];
    float rx = S.red[1] - minx, ry = S.red[3] - miny;
    float cs = fmaxf(fmaxf(S.red[4], fmaxf(rx, ry) * (1.0f / 31.0f)), 1.0f) * 1.0001f;
    float inv_cs = 1.0f / cs;
    int ncx = min(32, (int)(rx * inv_cs) + 1);
    int ncy = min(32, (int)(ry * inv_cs) + 1);

    int cix = 0, ciy = 0;
    if (real) {
        cix = min(ncx - 1, max(0, (int)((cx - minx) * inv_cs)));
        ciy = min(ncy - 1, max(0, (int)((cy - miny) * inv_cs)));
        int cid = ciy * 32 + cix;
        S.cellid[tid] = (unsigned short)cid;
        atomicAdd(&S.cellcnt[cid], 1);
    }
    __syncthreads();

    // exclusive scan of 1024 cell counts (512 threads x 2)
    {
        int c0 = S.cellcnt[2 * tid], c1 = S.cellcnt[2 * tid + 1];
        int s = c0 + c1;
        int incl = s;
        #pragma unroll
        for (int o = 1; o < 32; o <<= 1) {
            int n = __shfl_up_sync(0xFFFFFFFFu, incl, o);
            if (lane >= o) incl += n;
        }
        if (lane == 31) S.wtot[wid] = incl;
        __syncthreads();
        if (wid == 0) {
            int t = (lane < 16) ? S.wtot[lane] : 0;
            int ti = t;
            #pragma unroll
            for (int o = 1; o < 32; o <<= 1) {
                int n = __shfl_up_sync(0xFFFFFFFFu, ti, o);
                if (lane >= o) ti += n;
            }
            if (lane < 16) S.wtot[lane] = ti - t;
        }
        __syncthreads();
        int woff = S.wtot[wid];
        int excl = woff + incl - s;
        S.cellstart[2 * tid] = excl;
        S.cellstart[2 * tid + 1] = excl + c0;
    }
    __syncthreads();

    if (real) {
        int pos = atomicAdd(&S.cellstart[S.cellid[tid]], 1);
        S.order[pos] = (unsigned short)tid;
    }
    __syncthreads();

    // sparse pair search: 3x3 neighbor cells, only j > i, set bit on IoU > 0.5
    if (real) {
        int i = tid;
        float ix1 = S.bx1[i], iy1 = S.by1[i], ix2 = S.bx2[i], iy2 = S.by2[i];
        float ai = S.ar[i];
        bool any = false;
        for (int dy = -1; dy <= 1; dy++) {
            int yy = ciy + dy;
            if (yy < 0 || yy >= ncy) continue;
            for (int dxl = -1; dxl <= 1; dxl++) {
                int xx = cix + dxl;
                if (xx < 0 || xx >= ncx) continue;
                int c = yy * 32 + xx;
                int e = S.cellstart[c];
                int b = e - S.cellcnt[c];
                for (int k = b; k < e; k++) {
                    int j = S.order[k];
                    if (j <= i) continue;
                    float xx1 = fmaxf(ix1, S.bx1[j]);
                    float yy1 = fmaxf(iy1, S.by1[j]);
                    float xx2 = fminf(ix2, S.bx2[j]);
                    float yy2 = fminf(iy2, S.by2[j]);
                    float inter = fmaxf(xx2 - xx1, 0.0f) * fmaxf(yy2 - yy1, 0.0f);
                    if (3.0f * inter > ai + S.ar[j]) {
                        atomicOr(&S.big.sup[i][j >> 6], 1ull << (j & 63));
                        any = true;
                    }
                }
            }
        }
        if (any) atomicOr(&S.supmark[i >> 6], 1ull << (i & 63));
    }
    __syncthreads();

    // sparse greedy: visit only alive suppressor rows in index order (exact)
    if (tid == 0) {
        unsigned long long dropped[8] = {0,0,0,0,0,0,0,0};
        for (int w = 0; w < 8; w++) {
            unsigned long long rem = S.supmark[w] & S.keepw[w];
            while (true) {
                unsigned long long r2 = rem & ~dropped[w];
                if (!r2) break;
                int b = __ffsll((long long)r2) - 1;
                rem &= ~(1ull << b);
                int i = (w << 6) + b;
                #pragma unroll
                for (int w2 = 0; w2 < 8; w2++) dropped[w2] |= S.big.sup[i][w2];
            }
        }
        #pragma unroll
        for (int w = 0; w < 8; w++) S.keepw[w] &= ~dropped[w];
    }
    __syncthreads();

    float* okeep = out + 840000 + tbase;
    for (int r = tid; r < KTOP; r += NTH)
        okeep[r] = ((S.keepw[r >> 6] >> (r & 63)) & 1ull) ? 1.0f : 0.0f;
    if (tid == 0) g_cnt[task] = 0;   // restore invariant for next graph replay
}

// ---------------- launcher ----------------
extern "C" void kernel_launch(void* const* d_in, const int* in_sizes, int n_in,
                              void* d_out, int out_size) {
    const float *cls3 = nullptr, *cls4 = nullptr, *cls5 = nullptr;
    const float *reg3 = nullptr, *reg4 = nullptr, *reg5 = nullptr;
    for (int i = 0; i < n_in; i++) {
        switch (in_sizes[i]) {
            case 14155776: cls3 = (const float*)d_in[i]; break;
            case 7077888:  reg3 = (const float*)d_in[i]; break;
            case 3538944:  cls4 = (const float*)d_in[i]; break;
            case 1769472:  reg4 = (const float*)d_in[i]; break;
            case 884736:   cls5 = (const float*)d_in[i]; break;
            case 442368:   reg5 = (const float*)d_in[i]; break;
        }
    }
    float* out = (float*)d_out;
    cudaFuncSetAttribute(k_fused, cudaFuncAttributeMaxDynamicSharedMemorySize,
                         (int)sizeof(Fused));
    k_scan<<<672, 512>>>(cls3, cls4, cls5);
    k_fused<<<NTASK, NTH, sizeof(Fused)>>>(cls3, cls4, cls5, reg3, reg4, reg5, out);
}